// round 1
// baseline (speedup 1.0000x reference)
#include <cuda_runtime.h>

// Problem constants
#define Bdim 4
#define Cdim 16
#define Ldim 512
#define Hdim 1024

// Scratch: [2][B][L][C] floats, transposed so channel dim is contiguous.
// 2*4*512*16 = 65536 floats = 256 KB.
__device__ float g_scratch[2 * Bdim * Ldim * Cdim];

// ---------------------------------------------------------------------------
// Kernel A: per-row dot products.
// warp r in [0, 65536): tensor = r>>15 (0=start,1=end), idx = r & 32767
// idx decodes [b][c][l] (layout b,c,l,h with h contiguous, row = idx*1024).
// Result stored transposed at scratch[((tensor*B + b)*L + l)*C + c].
// ---------------------------------------------------------------------------
__global__ void __launch_bounds__(256) dot_kernel(
    const float* __restrict__ start,
    const float* __restrict__ end,
    const float* __restrict__ v)
{
    const unsigned warp = (blockIdx.x * blockDim.x + threadIdx.x) >> 5;
    const unsigned lane = threadIdx.x & 31;

    const unsigned tensor = warp >> 15;          // 0 or 1
    const unsigned idx    = warp & 32767;        // row within tensor

    const float4* row4 = (const float4*)((tensor ? end : start) + (size_t)idx * Hdim);
    const float4* v4   = (const float4*)(v + tensor * Hdim);

    float sum = 0.f;
#pragma unroll
    for (int k = 0; k < Hdim / 4 / 32; k++) {    // 8 iterations
        float4 a = row4[lane + 32 * k];
        float4 w = v4[lane + 32 * k];
        sum += a.x * w.x + a.y * w.y + a.z * w.z + a.w * w.w;
    }
#pragma unroll
    for (int o = 16; o; o >>= 1)
        sum += __shfl_xor_sync(0xFFFFFFFFu, sum, o);

    if (lane == 0) {
        const unsigned b = idx >> 13;            // / (C*L) = /8192
        const unsigned c = (idx >> 9) & (Cdim - 1);
        const unsigned l = idx & (Ldim - 1);
        g_scratch[((tensor * Bdim + b) * Ldim + l) * Cdim + c] = sum;
    }
}

// ---------------------------------------------------------------------------
// Kernel B: out[b,i,j,c] = s[b,i,c] + e[b,j,c], vectorized as float4 over c.
// Linear thread id g == output float4 index:
//   q = g & 3 (channel quarter), j = (g>>2)&511, i = (g>>11)&511, b = g>>20
// ---------------------------------------------------------------------------
__global__ void __launch_bounds__(256) add_kernel(float4* __restrict__ out)
{
    const unsigned g = blockIdx.x * blockDim.x + threadIdx.x;
    const unsigned q = g & 3;
    const unsigned j = (g >> 2) & (Ldim - 1);
    const unsigned i = (g >> 11) & (Ldim - 1);
    const unsigned b = g >> 20;

    const float4* sc4 = (const float4*)g_scratch;   // [2][B][L][4] float4
    float4 s = sc4[(b * Ldim + i) * (Cdim / 4) + q];
    float4 e = sc4[((Bdim + b) * Ldim + j) * (Cdim / 4) + q];

    out[g] = make_float4(s.x + e.x, s.y + e.y, s.z + e.z, s.w + e.w);
}

extern "C" void kernel_launch(void* const* d_in, const int* in_sizes, int n_in,
                              void* d_out, int out_size)
{
    const float* start = (const float*)d_in[0];
    const float* end   = (const float*)d_in[1];
    const float* v     = (const float*)d_in[2];
    float4* out = (float4*)d_out;

    // Kernel A: 65536 warps = 8192 blocks x 256 threads
    dot_kernel<<<(2 * Bdim * Cdim * Ldim) / 8, 256>>>(start, end, v);

    // Kernel B: B*L*L*C/4 = 4,194,304 float4s = 16384 blocks x 256 threads
    add_kernel<<<(Bdim * Ldim * Ldim * Cdim / 4) / 256, 256>>>(out);
}

// round 2
// speedup vs baseline: 1.2242x; 1.2242x over previous
#include <cuda_runtime.h>

// Problem constants
#define Bdim 4
#define Cdim 16
#define Ldim 512
#define Hdim 1024

// Scratch: [2][B][L][C] floats, channel contiguous. 256 KB.
__device__ float g_scratch[2 * Bdim * Ldim * Cdim];

// ---------------------------------------------------------------------------
// Kernel A v2: per-row dot products, 2 rows per warp for doubled MLP.
// warp w in [0, 32768): tensor = w>>14, rows idx0 = (w & 16383)*2, idx0+1.
// Streaming loads (__ldcs) on the 268 MB inputs to keep L2 for the epilogue.
// ---------------------------------------------------------------------------
__global__ void __launch_bounds__(256) dot_kernel(
    const float* __restrict__ start,
    const float* __restrict__ end,
    const float* __restrict__ v)
{
    const unsigned warp = (blockIdx.x * blockDim.x + threadIdx.x) >> 5;
    const unsigned lane = threadIdx.x & 31;

    const unsigned tensor = warp >> 14;              // 0 or 1
    const unsigned idx0   = (warp & 16383) * 2;      // first row within tensor

    const float* base = tensor ? end : start;
    const float4* row0 = (const float4*)(base + (size_t)idx0 * Hdim);
    const float4* row1 = (const float4*)(base + (size_t)(idx0 + 1) * Hdim);
    const float4* v4   = (const float4*)(v + tensor * Hdim);

    float sum0 = 0.f, sum1 = 0.f;
#pragma unroll
    for (int k = 0; k < Hdim / 4 / 32; k++) {        // 8 iterations
        float4 a0 = __ldcs(&row0[lane + 32 * k]);
        float4 a1 = __ldcs(&row1[lane + 32 * k]);
        float4 w  = v4[lane + 32 * k];
        sum0 += a0.x * w.x + a0.y * w.y + a0.z * w.z + a0.w * w.w;
        sum1 += a1.x * w.x + a1.y * w.y + a1.z * w.z + a1.w * w.w;
    }
#pragma unroll
    for (int o = 16; o; o >>= 1) {
        sum0 += __shfl_xor_sync(0xFFFFFFFFu, sum0, o);
        sum1 += __shfl_xor_sync(0xFFFFFFFFu, sum1, o);
    }

    if (lane == 0) {
        // decode [b][c][l] for both rows (l differs by 1, never crosses c)
        const unsigned b = idx0 >> 13;
        const unsigned c = (idx0 >> 9) & (Cdim - 1);
        const unsigned l = idx0 & (Ldim - 1);
        float* dst = &g_scratch[((tensor * Bdim + b) * Ldim + l) * Cdim + c];
        dst[0]    = sum0;
        dst[Cdim] = sum1;
    }
}

// ---------------------------------------------------------------------------
// Kernel B v2: smem-tiled broadcast add.
// Block covers (b, 8 i's, 64 j's, all 16 c) = 32 KB output.
// Smem: e tile 64x16 f (4 KB) + s tile 8x16 f (512 B).
// Thread t: q = t&3 (channel quarter), j = t>>2. Hoists e into regs,
// loops i storing 8 float4s; each warp store is 512 B contiguous.
// ---------------------------------------------------------------------------
__global__ void __launch_bounds__(256) add_kernel(float4* __restrict__ out)
{
    __shared__ float4 e_sm[64 * 4];   // [j][q]
    __shared__ float4 s_sm[8 * 4];    // [i][q]

    const unsigned bx = blockIdx.x;
    const unsigned jt = bx & 7;           // j tile (64 j each)
    const unsigned it = (bx >> 3) & 63;   // i tile (8 i each)
    const unsigned b  = bx >> 9;

    const unsigned t = threadIdx.x;
    const float4* sc4 = (const float4*)g_scratch;   // [2][B][L][4] float4

    // cooperative loads: e tile = 256 float4 (one per thread), s tile = 32 float4
    e_sm[t] = sc4[((Bdim + b) * Ldim + jt * 64) * (Cdim / 4) + t];
    if (t < 32)
        s_sm[t] = sc4[(b * Ldim + it * 8) * (Cdim / 4) + t];
    __syncthreads();

    const unsigned q = t & 3;
    const unsigned j = t >> 2;
    const float4 e = e_sm[j * 4 + q];

    // out float4 index: ((b*L + I)*L + J)*4 + q
    float4* dst = &out[(((b * Ldim + it * 8) * Ldim) + jt * 64 + j) * 4 + q];

#pragma unroll
    for (int i = 0; i < 8; i++) {
        float4 s = s_sm[i * 4 + q];
        dst[(size_t)i * Ldim * 4] =
            make_float4(s.x + e.x, s.y + e.y, s.z + e.z, s.w + e.w);
    }
}

extern "C" void kernel_launch(void* const* d_in, const int* in_sizes, int n_in,
                              void* d_out, int out_size)
{
    const float* start = (const float*)d_in[0];
    const float* end   = (const float*)d_in[1];
    const float* v     = (const float*)d_in[2];
    float4* out = (float4*)d_out;

    // Kernel A: 32768 warps (2 rows each) = 4096 blocks x 256 threads
    dot_kernel<<<4096, 256>>>(start, end, v);

    // Kernel B: 4 b x 64 i-tiles x 8 j-tiles = 2048 blocks x 256 threads
    add_kernel<<<2048, 256>>>(out);
}